// round 1
// baseline (speedup 1.0000x reference)
#include <cuda_runtime.h>
#include <math.h>

// ---------------- problem constants ----------------
#define Bb 4
#define Ll 512
#define Ee 256
#define Kk 8
#define Dd 6
#define LM 64
#define KN 4
#define Gg 32000
#define KE (Kk*Ee)          // 2048
#define TOK (Bb*Ll)         // 2048

// ---------------- scratch (static device memory; no allocations) ----------------
__device__ float g_z   [TOK*Ee];
__device__ float g_xsa [TOK*Ee];
__device__ float g_xsad[TOK*Ee];
__device__ float g_roll[TOK*Ee];
__device__ float g_t1  [TOK*Ee];
__device__ float g_q   [TOK*KE];           // also reused as y
__device__ float g_q2  [TOK*KE];           // also reused as t3
__device__ float g_h   [(long)Bb*Ll*Kk*Ll];
__device__ float g_y2  [(long)Bb*Ll*Kk*Ee];
__device__ float g_lptok[Bb*LM*Ee];
__device__ float g_xx0 [Bb*LM*KN*Ee];
__device__ float g_xx1 [Bb*LM*KN*Ee];
__device__ float g_s   [(long)Bb*LM*KN*Ll];
__device__ float g_xx  [Bb*LM*KN*Ee];
__device__ float g_v   [Bb*LM*KN*Ee];
__device__ float g_logits[(long)Bb*LM*KN*Gg];
__device__ float g_lse [Bb*LM*KN];
__device__ float g_tval[Bb*LM*KN];

// ---------------- reductions ----------------
__device__ __forceinline__ float warp_sum(float v){
    #pragma unroll
    for (int o=16;o;o>>=1) v += __shfl_xor_sync(0xffffffffu, v, o);
    return v;
}
__device__ __forceinline__ float warp_max(float v){
    #pragma unroll
    for (int o=16;o;o>>=1) v = fmaxf(v, __shfl_xor_sync(0xffffffffu, v, o));
    return v;
}
__device__ float block_sum256(float v){
    __shared__ float sh[8];
    int lane = threadIdx.x & 31, w = threadIdx.x >> 5;
    v = warp_sum(v);
    if (lane==0) sh[w] = v;
    __syncthreads();
    float r = (threadIdx.x < 8) ? sh[threadIdx.x] : 0.f;
    if (w==0){ r = warp_sum(r); if (lane==0) sh[0]=r; }
    __syncthreads();
    float out = sh[0];
    __syncthreads();
    return out;
}
__device__ float block_max256(float v){
    __shared__ float sh[8];
    int lane = threadIdx.x & 31, w = threadIdx.x >> 5;
    v = warp_max(v);
    if (lane==0) sh[w] = v;
    __syncthreads();
    float r = (threadIdx.x < 8) ? sh[threadIdx.x] : -INFINITY;
    if (w==0){ r = warp_max(r); if (lane==0) sh[0]=r; }
    __syncthreads();
    float out = sh[0];
    __syncthreads();
    return out;
}

// ---------------- generic tiled SGEMM ----------------
// C[M,N] (+= / =) op( A[M,K] * B ), B is [K,N] or [N,K] (TRANSB). Optional bias over N, relu.
// Batched via blockIdx.z with element strides sA/sB/sC.
template<int BM,int BN,int BK,int TM,int TN,bool TRANSB,bool RELU,bool ACCUM,bool BIAS>
__global__ void sgemm_k(const float* __restrict__ A, const float* __restrict__ B,
                        const float* __restrict__ bias, float* __restrict__ C,
                        int M, int N, int Kd, long sA, long sB, long sC)
{
    constexpr int THREADS = (BM/TM)*(BN/TN);
    __shared__ float As[BK][BM];
    __shared__ float Bs[BK][BN];
    const int bz = blockIdx.z;
    A += bz*sA; B += bz*sB; C += bz*sC;
    const int row0 = blockIdx.y*BM, col0 = blockIdx.x*BN;
    const int tid = threadIdx.x;
    const int tx = tid % (BN/TN);
    const int ty = tid / (BN/TN);
    float acc[TM][TN];
    #pragma unroll
    for (int i=0;i<TM;i++)
        #pragma unroll
        for (int j=0;j<TN;j++) acc[i][j]=0.f;

    for (int k0=0;k0<Kd;k0+=BK){
        #pragma unroll
        for (int t=tid; t<BM*BK; t+=THREADS){
            int m = t / BK, k = t % BK;
            As[k][m] = A[(long)(row0+m)*Kd + k0 + k];
        }
        if (!TRANSB){
            #pragma unroll
            for (int t=tid; t<BK*BN; t+=THREADS){
                int k = t / BN, n = t % BN;
                Bs[k][n] = B[(long)(k0+k)*N + col0 + n];
            }
        } else {
            #pragma unroll
            for (int t=tid; t<BK*BN; t+=THREADS){
                int n = t / BK, k = t % BK;
                Bs[k][n] = B[(long)(col0+n)*Kd + k0 + k];
            }
        }
        __syncthreads();
        #pragma unroll
        for (int k=0;k<BK;k++){
            float ra[TM], rb[TN];
            #pragma unroll
            for (int i=0;i<TM;i++) ra[i] = As[k][ty*TM+i];
            #pragma unroll
            for (int j=0;j<TN;j++) rb[j] = Bs[k][tx*TN+j];
            #pragma unroll
            for (int i=0;i<TM;i++)
                #pragma unroll
                for (int j=0;j<TN;j++)
                    acc[i][j] = fmaf(ra[i], rb[j], acc[i][j]);
        }
        __syncthreads();
    }
    #pragma unroll
    for (int i=0;i<TM;i++){
        long r = row0 + ty*TM + i;
        #pragma unroll
        for (int j=0;j<TN;j++){
            int c = col0 + tx*TN + j;
            float val = acc[i][j];
            if (BIAS)  val += bias[c];
            if (ACCUM) val += C[r*N + c];
            if (RELU)  val = fmaxf(val, 0.f);
            C[r*N + c] = val;
        }
    }
}

// ---------------- elementwise / reduction kernels ----------------
// z = norm(embed[masked]);  norm(x) = x / (1 + std(x, ddof=1))
__global__ void embed_norm_k(const int* __restrict__ masked, const float* __restrict__ embed,
                             float* __restrict__ z, float* __restrict__ xsa)
{
    int t = blockIdx.x;
    int g = masked[t];
    float v = embed[(long)g*Ee + threadIdx.x];
    float mean = block_sum256(v) * (1.f/Ee);
    float d = v - mean;
    float var = block_sum256(d*d) * (1.f/(Ee-1));
    float o = v / (1.f + sqrtf(var));
    z  [(long)t*Ee + threadIdx.x] = o;
    xsa[(long)t*Ee + threadIdx.x] = o;
}

// y[b,l] = x[b, (l-shift) mod L]
__global__ void roll_k(const float* __restrict__ x, float* __restrict__ y, int shift){
    int t = blockIdx.x; int b = t >> 9, l = t & 511;
    int src = (b << 9) | ((l - shift + Ll) & 511);
    y[(long)t*Ee + threadIdx.x] = x[(long)src*Ee + threadIdx.x];
}

// q2[b][l*K+k][e] = q[b*L+l][k*E+e]
__global__ void reshape_q_k(const float* __restrict__ q, float* __restrict__ q2){
    long idx = (long)blockIdx.x*256 + threadIdx.x;
    int e = idx & 255; long r = idx >> 8;
    int k = r & 7; int l = (r >> 3) & 511; int b = r >> 12;
    q2[idx] = q[((long)(b*Ll + l) << 11) + (k << 8) + e];
}

// y[b*L+l][k*E+e] = y2[b][l*K+k][e]
__global__ void reshape_y_k(const float* __restrict__ y2, float* __restrict__ y){
    long idx = (long)blockIdx.x*256 + threadIdx.x;   // linear over y2
    int e = idx & 255; long r = idx >> 8;
    int k = r & 7; int l = (r >> 3) & 511; int b = r >> 12;
    y[((long)(b*Ll + l) << 11) + (k << 8) + e] = y2[idx];
}

// softmax over rows of 512 with 1/16 scaling
__global__ void softmax_k(float* __restrict__ h){
    float* row = h + (long)blockIdx.x * Ll;
    float v0 = row[threadIdx.x]       * 0.0625f;
    float v1 = row[threadIdx.x + 256] * 0.0625f;
    float mx = block_max256(fmaxf(v0, v1));
    float e0 = expf(v0 - mx), e1 = expf(v1 - mx);
    float s = block_sum256(e0 + e1);
    float inv = 1.f / s;
    row[threadIdx.x]       = e0 * inv;
    row[threadIdx.x + 256] = e1 * inv;
}

// xsad = norm(xsad + xid); xsa = norm(xsa + 0.05*xsad)
__global__ void update_norm_k(const float* __restrict__ xsad, const float* __restrict__ xid,
                              float* __restrict__ xsa)
{
    long idx = (long)blockIdx.x*Ee + threadIdx.x;
    float u = xsad[idx] + xid[idx];
    float mean = block_sum256(u) * (1.f/Ee);
    float d = u - mean;
    float var = block_sum256(d*d) * (1.f/(Ee-1));
    float un = u / (1.f + sqrtf(var));
    float w = xsa[idx] + 0.05f * un;
    float mean2 = block_sum256(w) * (1.f/Ee);
    float d2 = w - mean2;
    float var2 = block_sum256(d2*d2) * (1.f/(Ee-1));
    xsa[idx] = w / (1.f + sqrtf(var2));
}

__global__ void gather_k(const int* __restrict__ mask, const float* __restrict__ xsa,
                         float* __restrict__ lptok){
    int r = blockIdx.x; int b = r >> 6; int p = mask[r];
    lptok[(long)r*Ee + threadIdx.x] = xsa[(long)(b*Ll + p)*Ee + threadIdx.x];
}

// xx1[b, j*KN+kn, e] = xx0[b, j, kn*E+e]
__global__ void reshape_xx_k(const float* __restrict__ xx0, float* __restrict__ xx1){
    long idx = (long)blockIdx.x*256 + threadIdx.x;
    int e = idx & 255; long r = idx >> 8;
    int kn = r & 3; int j = (r >> 2) & 63; int b = r >> 8;
    xx1[idx] = xx0[((long)(b*LM + j) << 10) + (kn << 8) + e];
}

// per-row (of 32000) logsumexp + target logit fetch
__global__ void lse_k(const float* __restrict__ logits, const int* __restrict__ unmasked,
                      const int* __restrict__ mask, float* __restrict__ lse, float* __restrict__ tval)
{
    int row = blockIdx.x;
    const float* p = logits + (long)row * Gg;
    float m = -INFINITY;
    for (int g = threadIdx.x; g < Gg; g += 256) m = fmaxf(m, p[g]);
    m = block_max256(m);
    float s = 0.f;
    for (int g = threadIdx.x; g < Gg; g += 256) s += expf(p[g] - m);
    s = block_sum256(s);
    if (threadIdx.x == 0){
        lse[row] = m + logf(s);
        int b = row >> 8, n = row & 255, j = n >> 2;
        int tg = unmasked[b*Ll + mask[b*LM + j]];
        tval[row] = p[tg];
    }
}

__global__ void final_k(const float* __restrict__ tval, const float* __restrict__ lse,
                        float* __restrict__ out)
{
    int b = blockIdx.x, j = threadIdx.x;   // 64 threads
    float a[KN]; float m = -INFINITY;
    #pragma unroll
    for (int kn=0;kn<KN;kn++){
        int r = ((b << 6) + j) * KN + kn;
        a[kn] = tval[r] - lse[r];
        m = fmaxf(m, a[kn]);
    }
    float s = 0.f;
    #pragma unroll
    for (int kn=0;kn<KN;kn++) s += expf(a[kn] - m);
    float cent = m + logf(s) - 1.3862943611198906f;   // - log(4)
    __shared__ float sh[64];
    sh[j] = cent; __syncthreads();
    for (int o=32;o;o>>=1){ if (j<o) sh[j] += sh[j+o]; __syncthreads(); }
    if (j==0) out[b] = -sh[0] / (float)LM;
}

// ---------------- host orchestration ----------------
extern "C" void kernel_launch(void* const* d_in, const int* in_sizes, int n_in,
                              void* d_out, int out_size)
{
    (void)in_sizes; (void)n_in; (void)out_size;
    const int*   masked   = (const int*)  d_in[0];
    const int*   unmasked = (const int*)  d_in[1];
    const int*   maskp    = (const int*)  d_in[2];
    const float* embed    = (const float*)d_in[3];
    const float* Wt       = (const float*)d_in[4];
    const float* bt       = (const float*)d_in[5];
    const float* Wtc      = (const float*)d_in[6];
    const float* Wq       = (const float*)d_in[7];
    const float* Wd       = (const float*)d_in[8];
    const float* Wo       = (const float*)d_in[9];
    const float* Wu       = (const float*)d_in[10];
    const float* Wem      = (const float*)d_in[11];
    const float* Wkc      = (const float*)d_in[12];
    const float* bkc      = (const float*)d_in[13];
    float* out = (float*)d_out;

    float *z,*xsa,*xsad,*rollb,*t1,*q,*q2,*h,*y2;
    float *lptok,*xx0,*xx1,*sbuf,*xx,*v,*logits,*lse,*tval;
    cudaGetSymbolAddress((void**)&z,      g_z);
    cudaGetSymbolAddress((void**)&xsa,    g_xsa);
    cudaGetSymbolAddress((void**)&xsad,   g_xsad);
    cudaGetSymbolAddress((void**)&rollb,  g_roll);
    cudaGetSymbolAddress((void**)&t1,     g_t1);
    cudaGetSymbolAddress((void**)&q,      g_q);
    cudaGetSymbolAddress((void**)&q2,     g_q2);
    cudaGetSymbolAddress((void**)&h,      g_h);
    cudaGetSymbolAddress((void**)&y2,     g_y2);
    cudaGetSymbolAddress((void**)&lptok,  g_lptok);
    cudaGetSymbolAddress((void**)&xx0,    g_xx0);
    cudaGetSymbolAddress((void**)&xx1,    g_xx1);
    cudaGetSymbolAddress((void**)&sbuf,   g_s);
    cudaGetSymbolAddress((void**)&xx,     g_xx);
    cudaGetSymbolAddress((void**)&v,      g_v);
    cudaGetSymbolAddress((void**)&logits, g_logits);
    cudaGetSymbolAddress((void**)&lse,    g_lse);
    cudaGetSymbolAddress((void**)&tval,   g_tval);

    // z = norm(embed[masked]); xsa = z
    embed_norm_k<<<TOK,256>>>(masked, embed, z, xsa);

    for (int d=0; d<Dd; d++){
        const float* wt  = Wt  + (long)d*Ee*Ee;
        const float* wtc = Wtc + (long)d*Ee*Ee;
        const float* wq  = Wq  + (long)d*KE*Ee;
        const float* wd  = Wd  + (long)d*KE*KE;
        const float* wo  = Wo  + (long)d*KE*Ee;
        const float* wu  = Wu  + (long)d*Ee*Ee;
        const float* btd = bt  + (long)d*Ee;

        // transitions
        roll_k<<<TOK,256>>>(xsa, rollb, 1);
        sgemm_k<64,64,16,4,4,false,true ,false,false><<<dim3(4,32,1),256>>>(rollb, wt , nullptr, t1  , TOK, Ee, Ee, 0,0,0);
        sgemm_k<64,64,16,4,4,false,false,false,false><<<dim3(4,32,1),256>>>(t1   , wtc, nullptr, xsad, TOK, Ee, Ee, 0,0,0);
        roll_k<<<TOK,256>>>(xsa, rollb, -1);
        sgemm_k<64,64,16,4,4,true ,true ,false,false><<<dim3(4,32,1),256>>>(rollb, wtc, nullptr, t1  , TOK, Ee, Ee, 0,0,0);
        sgemm_k<64,64,16,4,4,true ,false,true ,false><<<dim3(4,32,1),256>>>(t1   , wt , nullptr, xsad, TOK, Ee, Ee, 0,0,0);
        sgemm_k<64,64,16,4,4,true ,false,true ,true ><<<dim3(4,32,1),256>>>(z    , wu , btd    , xsad, TOK, Ee, Ee, 0,0,0);

        // attention
        sgemm_k<128,128,8,8,8,true,false,false,false><<<dim3(16,16,1),256>>>(xsa, wq, nullptr, q, TOK, KE, Ee, 0,0,0);
        reshape_q_k<<<16384,256>>>(q, q2);
        sgemm_k<128,128,8,8,8,true,false,false,false><<<dim3(4,32,Bb),256>>>(
            q2, xsa, nullptr, h, Ll*Kk, Ll, Ee, (long)Ll*Kk*Ee, (long)Ll*Ee, (long)Ll*Kk*Ll);
        softmax_k<<<Bb*Ll*Kk,256>>>(h);
        sgemm_k<128,128,8,8,8,false,false,false,false><<<dim3(2,32,Bb),256>>>(
            h, xsa, nullptr, y2, Ll*Kk, Ee, Ll, (long)Ll*Kk*Ll, (long)Ll*Ee, (long)Ll*Kk*Ee);
        reshape_y_k<<<16384,256>>>(y2, q);    // q now holds y [TOK, KE]

        // dense -> relu -> dense
        sgemm_k<128,128,8,8,8,true ,true ,false,false><<<dim3(16,16,1),256>>>(q , wd, nullptr, q2, TOK, KE, KE, 0,0,0);
        sgemm_k<64 ,64 ,16,4,4,false,false,false,false><<<dim3(4,32,1),256>>>(q2, wo, nullptr, t1, TOK, Ee, KE, 0,0,0);

        // double norm update
        update_norm_k<<<TOK,256>>>(xsad, t1, xsa);
    }

    // head
    gather_k<<<Bb*LM,256>>>(maskp, xsa, lptok);
    sgemm_k<64,64,16,4,4,true,false,false,true><<<dim3(16,4,1),256>>>(lptok, Wkc, bkc, xx0, Bb*LM, KN*Ee, Ee, 0,0,0);
    reshape_xx_k<<<1024,256>>>(xx0, xx1);
    sgemm_k<64,64,16,4,4,true ,false,false,false><<<dim3(8,4,Bb),256>>>(
        xx1, xsa, nullptr, sbuf, LM*KN, Ll, Ee, (long)LM*KN*Ee, (long)Ll*Ee, (long)LM*KN*Ll);
    sgemm_k<64,64,16,4,4,false,false,false,false><<<dim3(4,4,Bb),256>>>(
        sbuf, xsa, nullptr, xx, LM*KN, Ee, Ll, (long)LM*KN*Ll, (long)Ll*Ee, (long)LM*KN*Ee);
    sgemm_k<64,64,16,4,4,false,false,false,false><<<dim3(4,16,1),256>>>(xx, Wem, nullptr, v, Bb*LM*KN, Ee, Ee, 0,0,0);
    sgemm_k<128,128,8,8,8,true,false,false,false><<<dim3(250,8,1),256>>>(v, embed, nullptr, logits, Bb*LM*KN, Gg, Ee, 0,0,0);
    lse_k<<<Bb*LM*KN,256>>>(logits, unmasked, maskp, lse, tval);
    final_k<<<Bb,64>>>(tval, lse, out);
}

// round 2
// speedup vs baseline: 3.3812x; 3.3812x over previous
#include <cuda_runtime.h>
#include <math.h>
#include <stdint.h>

// ---------------- problem constants ----------------
#define Bb 4
#define Ll 512
#define Ee 256
#define Kk 8
#define Dd 6
#define LM 64
#define KN 4
#define Gg 32000
#define KE (Kk*Ee)          // 2048
#define TOK (Bb*Ll)         // 2048

// ---------------- scratch (static device memory; no allocations) ----------------
__device__ float g_z   [TOK*Ee];
__device__ float g_xsa [TOK*Ee];
__device__ float g_xsad[TOK*Ee];
__device__ float g_t1  [TOK*Ee];
__device__ float g_q   [TOK*KE];           // y buffer
__device__ float g_q2  [TOK*KE];           // q2 / dense-mid buffer
__device__ float g_h   [(long)Bb*Ll*Kk*Ll];
__device__ float g_lptok[Bb*LM*Ee];
__device__ float g_xx1 [Bb*LM*KN*Ee];
__device__ float g_s   [(long)Bb*LM*KN*Ll];
__device__ float g_xx  [Bb*LM*KN*Ee];
__device__ float g_v   [Bb*LM*KN*Ee];
__device__ float g_logits[(long)Bb*LM*KN*Gg];
__device__ float g_lse [Bb*LM*KN];
__device__ float g_tval[Bb*LM*KN];

// ---------------- reductions ----------------
__device__ __forceinline__ float warp_sum(float v){
    #pragma unroll
    for (int o=16;o;o>>=1) v += __shfl_xor_sync(0xffffffffu, v, o);
    return v;
}
__device__ __forceinline__ float warp_max(float v){
    #pragma unroll
    for (int o=16;o;o>>=1) v = fmaxf(v, __shfl_xor_sync(0xffffffffu, v, o));
    return v;
}
__device__ float block_sum256(float v){
    __shared__ float sh[8];
    int lane = threadIdx.x & 31, w = threadIdx.x >> 5;
    v = warp_sum(v);
    if (lane==0) sh[w] = v;
    __syncthreads();
    float r = (threadIdx.x < 8) ? sh[threadIdx.x] : 0.f;
    if (w==0){ r = warp_sum(r); if (lane==0) sh[0]=r; }
    __syncthreads();
    float out = sh[0];
    __syncthreads();
    return out;
}
__device__ float block_max256(float v){
    __shared__ float sh[8];
    int lane = threadIdx.x & 31, w = threadIdx.x >> 5;
    v = warp_max(v);
    if (lane==0) sh[w] = v;
    __syncthreads();
    float r = (threadIdx.x < 8) ? sh[threadIdx.x] : -INFINITY;
    if (w==0){ r = warp_max(r); if (lane==0) sh[0]=r; }
    __syncthreads();
    float out = sh[0];
    __syncthreads();
    return out;
}

// ---------------- tf32 helpers ----------------
__device__ __forceinline__ uint32_t f2tf32(float x){
    uint32_t r;
    asm("cvt.rna.tf32.f32 %0, %1;" : "=r"(r) : "f"(x));
    return r;
}
__device__ __forceinline__ void mma_tf32(float* d, const uint32_t* a, const uint32_t* b){
    asm volatile(
      "mma.sync.aligned.m16n8k8.row.col.f32.tf32.tf32.f32 "
      "{%0,%1,%2,%3}, {%4,%5,%6,%7}, {%8,%9}, {%0,%1,%2,%3};\n"
      : "+f"(d[0]),"+f"(d[1]),"+f"(d[2]),"+f"(d[3])
      : "r"(a[0]),"r"(a[1]),"r"(a[2]),"r"(a[3]), "r"(b[0]),"r"(b[1]));
}

// PMODE output index mapping:
// 0: C[bz*sC + r*N + c]
// 1: q2 perm: out[(r>>9)<<20 | (r&511)<<11 | c]       (r over TOK, c over KE)
// 2: y perm:  out[(bz*512 + (r>>3))<<11 | (r&7)<<8 | c]  (r over L*K, c over E)
// 3: xx1 perm: out[(r>>6)<<16 | (r&63)<<10 | c]       (r over B*LM, c over KN*E)
template<int PMODE>
__device__ __forceinline__ long out_index(int r, int c, int bz, int N, long sC){
    if (PMODE==0) return (long)bz*sC + (long)r*N + c;
    if (PMODE==1) return (((long)(r>>9))<<20) + ((long)(r&511)<<11) + c;
    if (PMODE==2) return (((long)(bz*512 + (r>>3)))<<11) + ((long)(r&7)<<8) + c;
    return (((long)(r>>6))<<16) + ((long)(r&63)<<10) + c;
}

// ---------------- tf32 tensor-core GEMM ----------------
// C[M,N] = op( A[M,K] * B ), B row-major [K,N] or [N,K] (TRANSB).
// COMP: 3xTF32 error-compensated (fp32-class accuracy).
// ROLL: A rows are circularly shifted within 512-row groups by rollShift.
template<int BM,int BN,int WM,int WN,bool TRANSB,bool RELU,bool ACCUM,bool BIAS,int PMODE,bool ROLL,bool COMP>
__global__ __launch_bounds__(256, 2)
void tgemm_k(const float* __restrict__ A, const float* __restrict__ B,
             const float* __restrict__ bias, float* __restrict__ C,
             int M, int N, int Kd, long sA, long sB, long sC, int rollShift)
{
    constexpr int BK  = 32;
    constexpr int LDA = BK + 4;     // 36 words/row; (4g+c) pattern conflict-free
    constexpr int LDB = BN + 4;     // (4c+g) pattern conflict-free
    constexpr int MI  = WM/16, NI = WN/8;
    constexpr int WCOLS = BN/WN;

    __shared__ uint32_t As[(COMP?2:1)*BM*LDA];
    __shared__ uint32_t Bs[(COMP?2:1)*BK*LDB];
    uint32_t* AsL = As + BM*LDA;
    uint32_t* BsL = Bs + BK*LDB;

    const int bz = blockIdx.z;
    const float* Ap = A + (long)bz*sA;
    const float* Bp = B + (long)bz*sB;

    const int row0 = blockIdx.y*BM, col0 = blockIdx.x*BN;
    const int tid  = threadIdx.x;
    const int warp = tid >> 5, lane = tid & 31;
    const int wy = warp / WCOLS, wx = warp % WCOLS;
    const int g = lane >> 2, c4 = lane & 3;

    float acc[MI][NI][4];
    #pragma unroll
    for (int i=0;i<MI;i++)
        #pragma unroll
        for (int j=0;j<NI;j++)
            #pragma unroll
            for (int t=0;t<4;t++) acc[i][j][t]=0.f;

    for (int k0=0; k0<Kd; k0+=BK){
        // ---- fill A tile (tf32 hi, optional lo) ----
        constexpr int AIT = BM*8/256;
        #pragma unroll
        for (int i=0;i<AIT;i++){
            int t = tid + i*256;
            int r = t >> 3, q = t & 7;
            int gr = row0 + r;
            if (ROLL) gr = (gr & ~511) | ((gr - rollShift) & 511);
            const float4 v = *(const float4*)(Ap + (long)gr*Kd + k0 + 4*q);
            uint32_t* dh = &As[r*LDA + 4*q];
            uint32_t h0=f2tf32(v.x), h1=f2tf32(v.y), h2=f2tf32(v.z), h3=f2tf32(v.w);
            dh[0]=h0; dh[1]=h1; dh[2]=h2; dh[3]=h3;
            if (COMP){
                uint32_t* dl = &AsL[r*LDA + 4*q];
                dl[0]=f2tf32(v.x - __uint_as_float(h0));
                dl[1]=f2tf32(v.y - __uint_as_float(h1));
                dl[2]=f2tf32(v.z - __uint_as_float(h2));
                dl[3]=f2tf32(v.w - __uint_as_float(h3));
            }
        }
        // ---- fill B tile ----
        if (!TRANSB){
            constexpr int BIT = BK*(BN/4)/256;
            #pragma unroll
            for (int i=0;i<BIT;i++){
                int t = tid + i*256;
                int k = t / (BN/4), j = t % (BN/4);
                const float4 v = *(const float4*)(Bp + (long)(k0+k)*N + col0 + 4*j);
                uint32_t* dh = &Bs[k*LDB + 4*j];
                uint32_t h0=f2tf32(v.x), h1=f2tf32(v.y), h2=f2tf32(v.z), h3=f2tf32(v.w);
                dh[0]=h0; dh[1]=h1; dh[2]=h2; dh[3]=h3;
                if (COMP){
                    uint32_t* dl = &BsL[k*LDB + 4*j];
                    dl[0]=f2tf32(v.x - __uint_as_float(h0));
                    dl[1]=f2tf32(v.y - __uint_as_float(h1));
                    dl[2]=f2tf32(v.z - __uint_as_float(h2));
                    dl[3]=f2tf32(v.w - __uint_as_float(h3));
                }
            }
        } else {
            constexpr int BIT = BN*8/256;
            #pragma unroll
            for (int i=0;i<BIT;i++){
                int t = tid + i*256;
                int n = t >> 3, q = t & 7;
                const float4 v = *(const float4*)(Bp + (long)(col0+n)*Kd + k0 + 4*q);
                uint32_t h0=f2tf32(v.x), h1=f2tf32(v.y), h2=f2tf32(v.z), h3=f2tf32(v.w);
                Bs[(4*q+0)*LDB + n]=h0; Bs[(4*q+1)*LDB + n]=h1;
                Bs[(4*q+2)*LDB + n]=h2; Bs[(4*q+3)*LDB + n]=h3;
                if (COMP){
                    BsL[(4*q+0)*LDB + n]=f2tf32(v.x - __uint_as_float(h0));
                    BsL[(4*q+1)*LDB + n]=f2tf32(v.y - __uint_as_float(h1));
                    BsL[(4*q+2)*LDB + n]=f2tf32(v.z - __uint_as_float(h2));
                    BsL[(4*q+3)*LDB + n]=f2tf32(v.w - __uint_as_float(h3));
                }
            }
        }
        __syncthreads();

        // ---- compute ----
        #pragma unroll
        for (int ks=0; ks<4; ks++){
            const int kb = ks*8;
            uint32_t af[MI][4], bf[NI][2];
            uint32_t afl[COMP?MI:1][4], bfl[COMP?NI:1][2];
            #pragma unroll
            for (int mi=0; mi<MI; mi++){
                int rr = wy*WM + mi*16;
                af[mi][0] = As[(rr+g  )*LDA + kb + c4];
                af[mi][1] = As[(rr+g+8)*LDA + kb + c4];
                af[mi][2] = As[(rr+g  )*LDA + kb + c4 + 4];
                af[mi][3] = As[(rr+g+8)*LDA + kb + c4 + 4];
                if (COMP){
                    afl[mi][0] = AsL[(rr+g  )*LDA + kb + c4];
                    afl[mi][1] = AsL[(rr+g+8)*LDA + kb + c4];
                    afl[mi][2] = AsL[(rr+g  )*LDA + kb + c4 + 4];
                    afl[mi][3] = AsL[(rr+g+8)*LDA + kb + c4 + 4];
                }
            }
            #pragma unroll
            for (int ni=0; ni<NI; ni++){
                int cc = wx*WN + ni*8 + g;
                bf[ni][0] = Bs[(kb + c4    )*LDB + cc];
                bf[ni][1] = Bs[(kb + c4 + 4)*LDB + cc];
                if (COMP){
                    bfl[ni][0] = BsL[(kb + c4    )*LDB + cc];
                    bfl[ni][1] = BsL[(kb + c4 + 4)*LDB + cc];
                }
            }
            #pragma unroll
            for (int mi=0; mi<MI; mi++)
                #pragma unroll
                for (int ni=0; ni<NI; ni++){
                    if (COMP){
                        mma_tf32(acc[mi][ni], afl[mi], bf[ni]);
                        mma_tf32(acc[mi][ni], af[mi], bfl[ni]);
                    }
                    mma_tf32(acc[mi][ni], af[mi], bf[ni]);
                }
        }
        __syncthreads();
    }

    // ---- epilogue ----
    #pragma unroll
    for (int mi=0; mi<MI; mi++){
        #pragma unroll
        for (int half=0; half<2; half++){
            int r = row0 + wy*WM + mi*16 + g + half*8;
            #pragma unroll
            for (int ni=0; ni<NI; ni++){
                int cc = col0 + wx*WN + ni*8 + 2*c4;
                float v0 = acc[mi][ni][half*2+0];
                float v1 = acc[mi][ni][half*2+1];
                if (BIAS){ v0 += bias[cc]; v1 += bias[cc+1]; }
                long idx = out_index<PMODE>(r, cc, bz, N, sC);
                if (ACCUM){ v0 += C[idx]; v1 += C[idx+1]; }
                if (RELU){ v0 = fmaxf(v0,0.f); v1 = fmaxf(v1,0.f); }
                C[idx]   = v0;
                C[idx+1] = v1;
            }
        }
    }
}

// ---------------- elementwise / reduction kernels ----------------
__global__ void embed_norm_k(const int* __restrict__ masked, const float* __restrict__ embed,
                             float* __restrict__ z, float* __restrict__ xsa)
{
    int t = blockIdx.x;
    int g = masked[t];
    float v = embed[(long)g*Ee + threadIdx.x];
    float mean = block_sum256(v) * (1.f/Ee);
    float d = v - mean;
    float var = block_sum256(d*d) * (1.f/(Ee-1));
    float o = v / (1.f + sqrtf(var));
    z  [(long)t*Ee + threadIdx.x] = o;
    xsa[(long)t*Ee + threadIdx.x] = o;
}

__global__ void softmax_k(float* __restrict__ h){
    float* row = h + (long)blockIdx.x * Ll;
    float v0 = row[threadIdx.x]       * 0.0625f;
    float v1 = row[threadIdx.x + 256] * 0.0625f;
    float mx = block_max256(fmaxf(v0, v1));
    float e0 = expf(v0 - mx), e1 = expf(v1 - mx);
    float s = block_sum256(e0 + e1);
    float inv = 1.f / s;
    row[threadIdx.x]       = e0 * inv;
    row[threadIdx.x + 256] = e1 * inv;
}

__global__ void update_norm_k(const float* __restrict__ xsad, const float* __restrict__ xid,
                              float* __restrict__ xsa)
{
    long idx = (long)blockIdx.x*Ee + threadIdx.x;
    float u = xsad[idx] + xid[idx];
    float mean = block_sum256(u) * (1.f/Ee);
    float d = u - mean;
    float var = block_sum256(d*d) * (1.f/(Ee-1));
    float un = u / (1.f + sqrtf(var));
    float w = xsa[idx] + 0.05f * un;
    float mean2 = block_sum256(w) * (1.f/Ee);
    float d2 = w - mean2;
    float var2 = block_sum256(d2*d2) * (1.f/(Ee-1));
    xsa[idx] = w / (1.f + sqrtf(var2));
}

__global__ void gather_k(const int* __restrict__ mask, const float* __restrict__ xsa,
                         float* __restrict__ lptok){
    int r = blockIdx.x; int b = r >> 6; int p = mask[r];
    lptok[(long)r*Ee + threadIdx.x] = xsa[(long)(b*Ll + p)*Ee + threadIdx.x];
}

__global__ void lse_k(const float* __restrict__ logits, const int* __restrict__ unmasked,
                      const int* __restrict__ mask, float* __restrict__ lse, float* __restrict__ tval)
{
    int row = blockIdx.x;
    const float* p = logits + (long)row * Gg;
    float m = -INFINITY;
    for (int g = threadIdx.x; g < Gg; g += 256) m = fmaxf(m, p[g]);
    m = block_max256(m);
    float s = 0.f;
    for (int g = threadIdx.x; g < Gg; g += 256) s += expf(p[g] - m);
    s = block_sum256(s);
    if (threadIdx.x == 0){
        lse[row] = m + logf(s);
        int b = row >> 8, n = row & 255, j = n >> 2;
        int tg = unmasked[b*Ll + mask[b*LM + j]];
        tval[row] = p[tg];
    }
}

__global__ void final_k(const float* __restrict__ tval, const float* __restrict__ lse,
                        float* __restrict__ out)
{
    int b = blockIdx.x, j = threadIdx.x;   // 64 threads
    float a[KN]; float m = -INFINITY;
    #pragma unroll
    for (int kn=0;kn<KN;kn++){
        int r = ((b << 6) + j) * KN + kn;
        a[kn] = tval[r] - lse[r];
        m = fmaxf(m, a[kn]);
    }
    float s = 0.f;
    #pragma unroll
    for (int kn=0;kn<KN;kn++) s += expf(a[kn] - m);
    float cent = m + logf(s) - 1.3862943611198906f;   // - log(4)
    __shared__ float sh[64];
    sh[j] = cent; __syncthreads();
    for (int o=32;o;o>>=1){ if (j<o) sh[j] += sh[j+o]; __syncthreads(); }
    if (j==0) out[b] = -sh[0] / (float)LM;
}

// ---------------- host orchestration ----------------
extern "C" void kernel_launch(void* const* d_in, const int* in_sizes, int n_in,
                              void* d_out, int out_size)
{
    (void)in_sizes; (void)n_in; (void)out_size;
    const int*   masked   = (const int*)  d_in[0];
    const int*   unmasked = (const int*)  d_in[1];
    const int*   maskp    = (const int*)  d_in[2];
    const float* embed    = (const float*)d_in[3];
    const float* Wt       = (const float*)d_in[4];
    const float* bt       = (const float*)d_in[5];
    const float* Wtc      = (const float*)d_in[6];
    const float* Wq       = (const float*)d_in[7];
    const float* Wd       = (const float*)d_in[8];
    const float* Wo       = (const float*)d_in[9];
    const float* Wu       = (const float*)d_in[10];
    const float* Wem      = (const float*)d_in[11];
    const float* Wkc      = (const float*)d_in[12];
    const float* bkc      = (const float*)d_in[13];
    float* out = (float*)d_out;

    float *z,*xsa,*xsad,*t1,*q,*q2,*h;
    float *lptok,*xx1,*sbuf,*xx,*v,*logits,*lse,*tval;
    cudaGetSymbolAddress((void**)&z,      g_z);
    cudaGetSymbolAddress((void**)&xsa,    g_xsa);
    cudaGetSymbolAddress((void**)&xsad,   g_xsad);
    cudaGetSymbolAddress((void**)&t1,     g_t1);
    cudaGetSymbolAddress((void**)&q,      g_q);
    cudaGetSymbolAddress((void**)&q2,     g_q2);
    cudaGetSymbolAddress((void**)&h,      g_h);
    cudaGetSymbolAddress((void**)&lptok,  g_lptok);
    cudaGetSymbolAddress((void**)&xx1,    g_xx1);
    cudaGetSymbolAddress((void**)&sbuf,   g_s);
    cudaGetSymbolAddress((void**)&xx,     g_xx);
    cudaGetSymbolAddress((void**)&v,      g_v);
    cudaGetSymbolAddress((void**)&logits, g_logits);
    cudaGetSymbolAddress((void**)&lse,    g_lse);
    cudaGetSymbolAddress((void**)&tval,   g_tval);

    // z = norm(embed[masked]); xsa = z
    embed_norm_k<<<TOK,256>>>(masked, embed, z, xsa);

    for (int d=0; d<Dd; d++){
        const float* wt  = Wt  + (long)d*Ee*Ee;
        const float* wtc = Wtc + (long)d*Ee*Ee;
        const float* wq  = Wq  + (long)d*KE*Ee;
        const float* wd  = Wd  + (long)d*KE*KE;
        const float* wo  = Wo  + (long)d*KE*Ee;
        const float* wu  = Wu  + (long)d*Ee*Ee;
        const float* btd = bt  + (long)d*Ee;

        // transitions (rolls fused into A-load)
        tgemm_k<64,64,32,16,false,true ,false,false,0,true ,false><<<dim3(4,32,1),256>>>(
            xsa, wt , nullptr, t1  , TOK, Ee, Ee, 0,0,0, 1);
        tgemm_k<64,64,32,16,false,false,false,false,0,false,false><<<dim3(4,32,1),256>>>(
            t1 , wtc, nullptr, xsad, TOK, Ee, Ee, 0,0,0, 0);
        tgemm_k<64,64,32,16,true ,true ,false,false,0,true ,false><<<dim3(4,32,1),256>>>(
            xsa, wtc, nullptr, t1  , TOK, Ee, Ee, 0,0,0, -1);
        tgemm_k<64,64,32,16,true ,false,true ,false,0,false,false><<<dim3(4,32,1),256>>>(
            t1 , wt , nullptr, xsad, TOK, Ee, Ee, 0,0,0, 0);
        tgemm_k<64,64,32,16,true ,false,true ,true ,0,false,false><<<dim3(4,32,1),256>>>(
            z  , wu , btd    , xsad, TOK, Ee, Ee, 0,0,0, 0);

        // attention: q2 written directly in permuted layout (PMODE1)
        tgemm_k<128,128,64,32,true ,false,false,false,1,false,false><<<dim3(16,16,1),256>>>(
            xsa, wq, nullptr, q2, TOK, KE, Ee, 0,0,0, 0);
        tgemm_k<128,128,64,32,true ,false,false,false,0,false,false><<<dim3(4,32,Bb),256>>>(
            q2, xsa, nullptr, h, Ll*Kk, Ll, Ee, (long)Ll*Kk*Ee, (long)Ll*Ee, (long)Ll*Kk*Ll, 0);
        softmax_k<<<Bb*Ll*Kk,256>>>(h);
        // y written directly back to [TOK,KE] layout (PMODE2)
        tgemm_k<128,128,64,32,false,false,false,false,2,false,false><<<dim3(2,32,Bb),256>>>(
            h, xsa, nullptr, q, Ll*Kk, Ee, Ll, (long)Ll*Kk*Ll, (long)Ll*Ee, 0, 0);

        // dense -> relu -> dense
        tgemm_k<128,128,64,32,true ,true ,false,false,0,false,false><<<dim3(16,16,1),256>>>(
            q , wd, nullptr, q2, TOK, KE, KE, 0,0,0, 0);
        tgemm_k<64,64,32,16,false,false,false,false,0,false,false><<<dim3(4,32,1),256>>>(
            q2, wo, nullptr, t1, TOK, Ee, KE, 0,0,0, 0);

        // double norm update
        update_norm_k<<<TOK,256>>>(xsad, t1, xsa);
    }

    // ---- head (compensated 3xTF32 for fp32-class accuracy) ----
    gather_k<<<Bb*LM,256>>>(maskp, xsa, lptok);
    // kchoice + fused reshape (PMODE3)
    tgemm_k<64,64,32,16,true ,false,false,true ,3,false,true ><<<dim3(16,4,1),256>>>(
        lptok, Wkc, bkc, xx1, Bb*LM, KN*Ee, Ee, 0,0,0, 0);
    tgemm_k<64,64,32,16,true ,false,false,false,0,false,true ><<<dim3(8,4,Bb),256>>>(
        xx1, xsa, nullptr, sbuf, LM*KN, Ll, Ee, (long)LM*KN*Ee, (long)Ll*Ee, (long)LM*KN*Ll, 0);
    tgemm_k<64,64,32,16,false,false,false,false,0,false,true ><<<dim3(4,4,Bb),256>>>(
        sbuf, xsa, nullptr, xx, LM*KN, Ee, Ll, (long)LM*KN*Ll, (long)Ll*Ee, (long)LM*KN*Ee, 0);
    tgemm_k<64,64,32,16,false,false,false,false,0,false,true ><<<dim3(4,16,1),256>>>(
        xx, Wem, nullptr, v, Bb*LM*KN, Ee, Ee, 0,0,0, 0);
    tgemm_k<64,64,32,16,true ,false,false,false,0,false,true ><<<dim3(500,16,1),256>>>(
        v, embed, nullptr, logits, Bb*LM*KN, Gg, Ee, 0,0,0, 0);
    lse_k<<<Bb*LM*KN,256>>>(logits, unmasked, maskp, lse, tval);
    final_k<<<Bb,64>>>(tval, lse, out);
}

// round 3
// speedup vs baseline: 4.4591x; 1.3188x over previous
#include <cuda_runtime.h>
#include <math.h>
#include <stdint.h>

// ---------------- problem constants ----------------
#define Bb 4
#define Ll 512
#define Ee 256
#define Kk 8
#define Dd 6
#define LM 64
#define KN 4
#define Gg 32000
#define KE (Kk*Ee)          // 2048
#define TOK (Bb*Ll)         // 2048

// ---------------- scratch (static device memory; no allocations) ----------------
__device__ float g_xsa [TOK*Ee];
__device__ float g_xsad[TOK*Ee];
__device__ float g_t1  [TOK*Ee];
__device__ float g_q   [TOK*KE];
__device__ float g_q2  [TOK*KE];
__device__ float g_h   [(long)Bb*Ll*Kk*Ll];
__device__ float g_acat[TOK*768];                 // [t1a | t1b | z]
__device__ float g_wcat1[Dd*2*Ee*Ee];             // per layer: [wt][wtc^T]
__device__ float g_wcat2[Dd*3*Ee*Ee];             // per layer: [wtc; wt^T; wu^T]
// tf32 hi/lo splits for the compensated head
__device__ float g_ehi[(long)Gg*Ee],  g_elo[(long)Gg*Ee];
__device__ float g_xsahi[TOK*Ee],     g_xsalo[TOK*Ee];
__device__ float g_wkchi[KN*Ee*Ee],   g_wkclo[KN*Ee*Ee];
__device__ float g_wemhi[Ee*Ee],      g_wemlo[Ee*Ee];
__device__ float g_lpthi[Bb*LM*Ee],   g_lptlo[Bb*LM*Ee];
__device__ float g_xx1hi[Bb*LM*KN*Ee],g_xx1lo[Bb*LM*KN*Ee];
__device__ float g_shi[(long)Bb*LM*KN*Ll], g_slo[(long)Bb*LM*KN*Ll];
__device__ float g_xxhi[Bb*LM*KN*Ee], g_xxlo[Bb*LM*KN*Ee];
__device__ float g_vhi[Bb*LM*KN*Ee],  g_vlo[Bb*LM*KN*Ee];
__device__ float g_logits[(long)Bb*LM*KN*Gg];
__device__ float g_lse [Bb*LM*KN];
__device__ float g_tval[Bb*LM*KN];

// ---------------- reductions ----------------
__device__ __forceinline__ float warp_sum(float v){
    #pragma unroll
    for (int o=16;o;o>>=1) v += __shfl_xor_sync(0xffffffffu, v, o);
    return v;
}
__device__ __forceinline__ float warp_max(float v){
    #pragma unroll
    for (int o=16;o;o>>=1) v = fmaxf(v, __shfl_xor_sync(0xffffffffu, v, o));
    return v;
}
__device__ float block_sum256(float v){
    __shared__ float sh[8];
    int lane = threadIdx.x & 31, w = threadIdx.x >> 5;
    v = warp_sum(v);
    if (lane==0) sh[w] = v;
    __syncthreads();
    float r = (threadIdx.x < 8) ? sh[threadIdx.x] : 0.f;
    if (w==0){ r = warp_sum(r); if (lane==0) sh[0]=r; }
    __syncthreads();
    float out = sh[0];
    __syncthreads();
    return out;
}
__device__ float block_max256(float v){
    __shared__ float sh[8];
    int lane = threadIdx.x & 31, w = threadIdx.x >> 5;
    v = warp_max(v);
    if (lane==0) sh[w] = v;
    __syncthreads();
    float r = (threadIdx.x < 8) ? sh[threadIdx.x] : -INFINITY;
    if (w==0){ r = warp_max(r); if (lane==0) sh[0]=r; }
    __syncthreads();
    float out = sh[0];
    __syncthreads();
    return out;
}

// ---------------- tf32 / cp.async helpers ----------------
__device__ __forceinline__ uint32_t tfrag(float x){
    uint32_t r;
    asm("cvt.rna.tf32.f32 %0, %1;" : "=r"(r) : "f"(x));
    return r;
}
__device__ __forceinline__ void mma_tf32(float* d, const uint32_t* a, const uint32_t* b){
    asm volatile(
      "mma.sync.aligned.m16n8k8.row.col.f32.tf32.tf32.f32 "
      "{%0,%1,%2,%3}, {%4,%5,%6,%7}, {%8,%9}, {%0,%1,%2,%3};\n"
      : "+f"(d[0]),"+f"(d[1]),"+f"(d[2]),"+f"(d[3])
      : "r"(a[0]),"r"(a[1]),"r"(a[2]),"r"(a[3]), "r"(b[0]),"r"(b[1]));
}
__device__ __forceinline__ void cp16(float* s, const float* g){
    uint32_t sa = (uint32_t)__cvta_generic_to_shared(s);
    asm volatile("cp.async.ca.shared.global [%0], [%1], 16;\n" :: "r"(sa), "l"(g));
}
__device__ __forceinline__ void cp_commit(){ asm volatile("cp.async.commit_group;\n" ::); }
template<int W> __device__ __forceinline__ void cp_wait(){ asm volatile("cp.async.wait_group %0;\n" :: "n"(W)); }

// PMODE output index mapping:
// 0: bz*sC + r*N + c
// 1: q2 perm  (r over TOK, c over KE)
// 2: y perm   (r over L*K, c over E)
// 3: xx1 perm (r over B*LM, c over KN*E)
// 4: stage1 concat: r*768 + bz*256 + c
template<int PMODE>
__device__ __forceinline__ long out_index(int r, int c, int bz, int N, long sC){
    if (PMODE==0) return (long)bz*sC + (long)r*N + c;
    if (PMODE==1) return (((long)(r>>9))<<20) + ((long)(r&511)<<11) + c;
    if (PMODE==2) return (((long)(bz*512 + (r>>3)))<<11) + ((long)(r&7)<<8) + c;
    if (PMODE==3) return (((long)(r>>6))<<16) + ((long)(r&63)<<10) + c;
    return (long)r*768 + ((long)bz<<8) + c;
}

template<int BM,int BN,bool TRANSB,bool COMP>
constexpr int smem_bytes(){
    return 2*(COMP?2:1)*(BM*36 + (TRANSB? BN*36 : 32*(BN+8)))*4;
}

// ---------------- pipelined tf32 tensor-core GEMM ----------------
// C[M,N] = op( A[M,K] * B ).  TRANSB: B is [N,K] row-major (pitch Kd), else [K,N] (pitch N).
// A pitch = lda. COMP: 3xTF32 using pre-split hi/lo operand arrays.
// OSPLIT: write output as tf32 hi/lo pair (C=hi, Clo=lo) instead of fp32.
// ROLLMODE: 0 none; 1 circular shift rows by rollShift within 512-row groups;
//           2 per-batch shift (+rollShift for bz=0, -rollShift for bz=1).
template<int BM,int BN,int WM,int WN,bool TRANSB,bool RELU,bool BIAS,int PMODE,int ROLLMODE,bool COMP,bool OSPLIT>
__global__ __launch_bounds__(256, 2)
void tgemm_k(const float* __restrict__ A, const float* __restrict__ Alo,
             const float* __restrict__ B, const float* __restrict__ Blo,
             const float* __restrict__ bias,
             float* __restrict__ C, float* __restrict__ Clo,
             int M, int N, int Kd, int lda,
             long sA, long sB, long sC, int rollShift)
{
    constexpr int ASZ = BM*36;
    constexpr int BSZ = TRANSB ? BN*36 : 32*(BN+8);
    constexpr int NST = COMP ? 2 : 1;
    constexpr int STG = NST*(ASZ+BSZ);
    constexpr int MI  = WM/16, NI = WN/8;
    constexpr int WCOLS = BN/WN;
    constexpr int LDN = BN+8;

    extern __shared__ float sm[];

    const int bz = blockIdx.z;
    const float* Ap  = A   + (long)bz*sA;
    const float* Alp = COMP ? Alo + (long)bz*sA : nullptr;
    const float* Bp  = B   + (long)bz*sB;
    const float* Blp = COMP ? Blo + (long)bz*sB : nullptr;

    int rs = 0;
    if (ROLLMODE==1) rs = rollShift;
    if (ROLLMODE==2) rs = (bz==0) ? rollShift : -rollShift;

    const int row0 = blockIdx.y*BM, col0 = blockIdx.x*BN;
    const int tid  = threadIdx.x;
    const int warp = tid >> 5, lane = tid & 31;
    const int wy = warp / WCOLS, wx = warp % WCOLS;
    const int g = lane >> 2, c4 = lane & 3;

    auto load_tile = [&](int kt, int st){
        float* base = sm + st*STG;
        float* Ah = base;
        float* Al = base + ASZ;
        float* Bh = base + NST*ASZ;
        float* Bl = Bh + BSZ;
        const int k0 = kt*32;
        #pragma unroll
        for (int i=0;i<BM*8/256;i++){
            int ch = tid + i*256; int r = ch>>3, q = ch&7;
            int gr = row0 + r;
            if (ROLLMODE) gr = (gr & ~511) | ((gr - rs) & 511);
            long go = (long)gr*lda + k0 + 4*q;
            cp16(Ah + r*36 + 4*q, Ap + go);
            if (COMP) cp16(Al + r*36 + 4*q, Alp + go);
        }
        if (TRANSB){
            #pragma unroll
            for (int i=0;i<BN*8/256;i++){
                int ch = tid + i*256; int n = ch>>3, q = ch&7;
                long go = (long)(col0+n)*Kd + k0 + 4*q;
                cp16(Bh + n*36 + 4*q, Bp + go);
                if (COMP) cp16(Bl + n*36 + 4*q, Blp + go);
            }
        } else {
            #pragma unroll
            for (int i=0;i<(32*BN/4)/256;i++){
                int ch = tid + i*256; int k = ch/(BN/4), j = ch%(BN/4);
                long go = (long)(k0+k)*N + col0 + 4*j;
                cp16(Bh + k*LDN + 4*j, Bp + go);
                if (COMP) cp16(Bl + k*LDN + 4*j, Blp + go);
            }
        }
        cp_commit();
    };

    float acc[MI][NI][4];
    #pragma unroll
    for (int i=0;i<MI;i++)
        #pragma unroll
        for (int j=0;j<NI;j++)
            #pragma unroll
            for (int t=0;t<4;t++) acc[i][j][t]=0.f;

    const int nit = Kd/32;
    load_tile(0, 0);

    for (int it=0; it<nit; it++){
        if (it+1 < nit){ load_tile(it+1, (it+1)&1); cp_wait<1>(); }
        else           { cp_wait<0>(); }
        __syncthreads();

        float* base = sm + (it&1)*STG;
        float* Ah = base;
        float* Al = base + ASZ;
        float* Bh = base + NST*ASZ;
        float* Bl = Bh + BSZ;

        #pragma unroll
        for (int ks=0; ks<4; ks++){
            const int kb = ks*8;
            uint32_t af[MI][4], bf[NI][2];
            uint32_t afl[COMP?MI:1][4], bfl[COMP?NI:1][2];
            #pragma unroll
            for (int mi=0; mi<MI; mi++){
                int rr = wy*WM + mi*16;
                float v0 = Ah[(rr+g  )*36 + kb + c4];
                float v1 = Ah[(rr+g+8)*36 + kb + c4];
                float v2 = Ah[(rr+g  )*36 + kb + c4 + 4];
                float v3 = Ah[(rr+g+8)*36 + kb + c4 + 4];
                if (COMP){
                    af[mi][0]=__float_as_uint(v0); af[mi][1]=__float_as_uint(v1);
                    af[mi][2]=__float_as_uint(v2); af[mi][3]=__float_as_uint(v3);
                    afl[mi][0]=__float_as_uint(Al[(rr+g  )*36 + kb + c4]);
                    afl[mi][1]=__float_as_uint(Al[(rr+g+8)*36 + kb + c4]);
                    afl[mi][2]=__float_as_uint(Al[(rr+g  )*36 + kb + c4 + 4]);
                    afl[mi][3]=__float_as_uint(Al[(rr+g+8)*36 + kb + c4 + 4]);
                } else {
                    af[mi][0]=tfrag(v0); af[mi][1]=tfrag(v1);
                    af[mi][2]=tfrag(v2); af[mi][3]=tfrag(v3);
                }
            }
            #pragma unroll
            for (int ni=0; ni<NI; ni++){
                int cc = wx*WN + ni*8 + g;
                float w0, w1;
                if (TRANSB){
                    w0 = Bh[cc*36 + kb + c4];
                    w1 = Bh[cc*36 + kb + c4 + 4];
                } else {
                    w0 = Bh[(kb + c4    )*LDN + cc];
                    w1 = Bh[(kb + c4 + 4)*LDN + cc];
                }
                if (COMP){
                    bf[ni][0]=__float_as_uint(w0); bf[ni][1]=__float_as_uint(w1);
                    if (TRANSB){
                        bfl[ni][0]=__float_as_uint(Bl[cc*36 + kb + c4]);
                        bfl[ni][1]=__float_as_uint(Bl[cc*36 + kb + c4 + 4]);
                    } else {
                        bfl[ni][0]=__float_as_uint(Bl[(kb + c4    )*LDN + cc]);
                        bfl[ni][1]=__float_as_uint(Bl[(kb + c4 + 4)*LDN + cc]);
                    }
                } else {
                    bf[ni][0]=tfrag(w0); bf[ni][1]=tfrag(w1);
                }
            }
            #pragma unroll
            for (int mi=0; mi<MI; mi++)
                #pragma unroll
                for (int ni=0; ni<NI; ni++){
                    if (COMP){
                        mma_tf32(acc[mi][ni], afl[mi], bf[ni]);
                        mma_tf32(acc[mi][ni], af[mi], bfl[ni]);
                    }
                    mma_tf32(acc[mi][ni], af[mi], bf[ni]);
                }
        }
        __syncthreads();
    }

    // ---- epilogue ----
    #pragma unroll
    for (int mi=0; mi<MI; mi++){
        #pragma unroll
        for (int half=0; half<2; half++){
            int r = row0 + wy*WM + mi*16 + g + half*8;
            #pragma unroll
            for (int ni=0; ni<NI; ni++){
                int cc = col0 + wx*WN + ni*8 + 2*c4;
                float v0 = acc[mi][ni][half*2+0];
                float v1 = acc[mi][ni][half*2+1];
                if (BIAS){ v0 += bias[cc]; v1 += bias[cc+1]; }
                if (RELU){ v0 = fmaxf(v0,0.f); v1 = fmaxf(v1,0.f); }
                long idx = out_index<PMODE>(r, cc, bz, N, sC);
                if (OSPLIT){
                    float h0 = __uint_as_float(tfrag(v0));
                    float h1 = __uint_as_float(tfrag(v1));
                    C[idx]     = h0;
                    C[idx+1]   = h1;
                    Clo[idx]   = __uint_as_float(tfrag(v0 - h0));
                    Clo[idx+1] = __uint_as_float(tfrag(v1 - h1));
                } else {
                    *(float2*)(C + idx) = make_float2(v0, v1);
                }
            }
        }
    }
}

// ---------------- weight prep: concatenated transition blocks ----------------
__global__ void prep_w_k(const float* __restrict__ Wt, const float* __restrict__ Wtc,
                         const float* __restrict__ Wu,
                         float* __restrict__ wcat1, float* __restrict__ wcat2)
{
    long idx = (long)blockIdx.x*1024 + threadIdx.x;
    if (idx >= (long)Dd*5*Ee*Ee) return;
    int d = idx / (5*65536);
    int r = idx % (5*65536);
    int which = r / 65536;
    int e = r % 65536;
    int k = e >> 8, n = e & 255;
    long wb = (long)d*65536;
    if      (which==0) wcat1[(long)d*131072 +          e] = Wt [wb + (long)k*256 + n];
    else if (which==1) wcat1[(long)d*131072 + 65536 +  e] = Wtc[wb + (long)n*256 + k];
    else if (which==2) wcat2[(long)d*196608 + (long)(    k)*256 + n] = Wtc[wb + (long)k*256 + n];
    else if (which==3) wcat2[(long)d*196608 + (long)(256+k)*256 + n] = Wt [wb + (long)n*256 + k];
    else               wcat2[(long)d*196608 + (long)(512+k)*256 + n] = Wu [wb + (long)n*256 + k];
}

// ---------------- split: fp32 -> tf32 hi/lo ----------------
__global__ void split_k(const float* __restrict__ in, float* __restrict__ hi,
                        float* __restrict__ lo, long n)
{
    long i = (long)blockIdx.x*256 + threadIdx.x;
    if (i >= n) return;
    float v = in[i];
    float h = __uint_as_float(tfrag(v));
    hi[i] = h;
    lo[i] = __uint_as_float(tfrag(v - h));
}

// ---------------- elementwise / reduction kernels ----------------
// z = norm(embed[masked]); xsa = z; also write z into Acat cols [512,768)
__global__ void embed_norm_k(const int* __restrict__ masked, const float* __restrict__ embed,
                             float* __restrict__ xsa, float* __restrict__ acat)
{
    int t = blockIdx.x;
    int g = masked[t];
    float v = embed[(long)g*Ee + threadIdx.x];
    float mean = block_sum256(v) * (1.f/Ee);
    float d = v - mean;
    float var = block_sum256(d*d) * (1.f/(Ee-1));
    float o = v / (1.f + sqrtf(var));
    xsa [(long)t*Ee + threadIdx.x] = o;
    acat[(long)t*768 + 512 + threadIdx.x] = o;
}

__global__ void softmax_k(float* __restrict__ h){
    float* row = h + (long)blockIdx.x * Ll;
    float v0 = row[threadIdx.x]       * 0.0625f;
    float v1 = row[threadIdx.x + 256] * 0.0625f;
    float mx = block_max256(fmaxf(v0, v1));
    float e0 = expf(v0 - mx), e1 = expf(v1 - mx);
    float s = block_sum256(e0 + e1);
    float inv = 1.f / s;
    row[threadIdx.x]       = e0 * inv;
    row[threadIdx.x + 256] = e1 * inv;
}

__global__ void update_norm_k(const float* __restrict__ xsad, const float* __restrict__ xid,
                              float* __restrict__ xsa)
{
    long idx = (long)blockIdx.x*Ee + threadIdx.x;
    float u = xsad[idx] + xid[idx];
    float mean = block_sum256(u) * (1.f/Ee);
    float d = u - mean;
    float var = block_sum256(d*d) * (1.f/(Ee-1));
    float un = u / (1.f + sqrtf(var));
    float w = xsa[idx] + 0.05f * un;
    float mean2 = block_sum256(w) * (1.f/Ee);
    float d2 = w - mean2;
    float var2 = block_sum256(d2*d2) * (1.f/(Ee-1));
    xsa[idx] = w / (1.f + sqrtf(var2));
}

// gather masked tokens and split to hi/lo
__global__ void gather_split_k(const int* __restrict__ mask, const float* __restrict__ xsa,
                               float* __restrict__ hi, float* __restrict__ lo){
    int r = blockIdx.x; int b = r >> 6; int p = mask[r];
    float v = xsa[(long)(b*Ll + p)*Ee + threadIdx.x];
    float h = __uint_as_float(tfrag(v));
    hi[(long)r*Ee + threadIdx.x] = h;
    lo[(long)r*Ee + threadIdx.x] = __uint_as_float(tfrag(v - h));
}

__global__ void lse_k(const float* __restrict__ logits, const int* __restrict__ unmasked,
                      const int* __restrict__ mask, float* __restrict__ lse, float* __restrict__ tval)
{
    int row = blockIdx.x;
    const float* p = logits + (long)row * Gg;
    float m = -INFINITY;
    for (int g = threadIdx.x; g < Gg; g += 256) m = fmaxf(m, p[g]);
    m = block_max256(m);
    float s = 0.f;
    for (int g = threadIdx.x; g < Gg; g += 256) s += expf(p[g] - m);
    s = block_sum256(s);
    if (threadIdx.x == 0){
        lse[row] = m + logf(s);
        int b = row >> 8, n = row & 255, j = n >> 2;
        int tg = unmasked[b*Ll + mask[b*LM + j]];
        tval[row] = p[tg];
    }
}

__global__ void final_k(const float* __restrict__ tval, const float* __restrict__ lse,
                        float* __restrict__ out)
{
    int b = blockIdx.x, j = threadIdx.x;   // 64 threads
    float a[KN]; float m = -INFINITY;
    #pragma unroll
    for (int kn=0;kn<KN;kn++){
        int r = ((b << 6) + j) * KN + kn;
        a[kn] = tval[r] - lse[r];
        m = fmaxf(m, a[kn]);
    }
    float s = 0.f;
    #pragma unroll
    for (int kn=0;kn<KN;kn++) s += expf(a[kn] - m);
    float cent = m + logf(s) - 1.3862943611198906f;   // - log(4)
    __shared__ float sh[64];
    sh[j] = cent; __syncthreads();
    for (int o=32;o;o>>=1){ if (j<o) sh[j] += sh[j+o]; __syncthreads(); }
    if (j==0) out[b] = -sh[0] / (float)LM;
}

// ---------------- host orchestration ----------------
extern "C" void kernel_launch(void* const* d_in, const int* in_sizes, int n_in,
                              void* d_out, int out_size)
{
    (void)in_sizes; (void)n_in; (void)out_size;
    const int*   masked   = (const int*)  d_in[0];
    const int*   unmasked = (const int*)  d_in[1];
    const int*   maskp    = (const int*)  d_in[2];
    const float* embed    = (const float*)d_in[3];
    const float* Wt       = (const float*)d_in[4];
    const float* bt       = (const float*)d_in[5];
    const float* Wtc      = (const float*)d_in[6];
    const float* Wq       = (const float*)d_in[7];
    const float* Wd       = (const float*)d_in[8];
    const float* Wo       = (const float*)d_in[9];
    const float* Wu       = (const float*)d_in[10];
    const float* Wem      = (const float*)d_in[11];
    const float* Wkc      = (const float*)d_in[12];
    const float* bkc      = (const float*)d_in[13];
    float* out = (float*)d_out;

    float *xsa,*xsad,*t1,*q,*q2,*h,*acat,*wcat1,*wcat2;
    float *ehi,*elo,*xsahi,*xsalo,*wkchi,*wkclo,*wemhi,*wemlo;
    float *lpthi,*lptlo,*xx1hi,*xx1lo,*shi,*slo,*xxhi,*xxlo,*vhi,*vlo;
    float *logits,*lse,*tval;
    cudaGetSymbolAddress((void**)&xsa,    g_xsa);
    cudaGetSymbolAddress((void**)&xsad,   g_xsad);
    cudaGetSymbolAddress((void**)&t1,     g_t1);
    cudaGetSymbolAddress((void**)&q,      g_q);
    cudaGetSymbolAddress((void**)&q2,     g_q2);
    cudaGetSymbolAddress((void**)&h,      g_h);
    cudaGetSymbolAddress((void**)&acat,   g_acat);
    cudaGetSymbolAddress((void**)&wcat1,  g_wcat1);
    cudaGetSymbolAddress((void**)&wcat2,  g_wcat2);
    cudaGetSymbolAddress((void**)&ehi,    g_ehi);
    cudaGetSymbolAddress((void**)&elo,    g_elo);
    cudaGetSymbolAddress((void**)&xsahi,  g_xsahi);
    cudaGetSymbolAddress((void**)&xsalo,  g_xsalo);
    cudaGetSymbolAddress((void**)&wkchi,  g_wkchi);
    cudaGetSymbolAddress((void**)&wkclo,  g_wkclo);
    cudaGetSymbolAddress((void**)&wemhi,  g_wemhi);
    cudaGetSymbolAddress((void**)&wemlo,  g_wemlo);
    cudaGetSymbolAddress((void**)&lpthi,  g_lpthi);
    cudaGetSymbolAddress((void**)&lptlo,  g_lptlo);
    cudaGetSymbolAddress((void**)&xx1hi,  g_xx1hi);
    cudaGetSymbolAddress((void**)&xx1lo,  g_xx1lo);
    cudaGetSymbolAddress((void**)&shi,    g_shi);
    cudaGetSymbolAddress((void**)&slo,    g_slo);
    cudaGetSymbolAddress((void**)&xxhi,   g_xxhi);
    cudaGetSymbolAddress((void**)&xxlo,   g_xxlo);
    cudaGetSymbolAddress((void**)&vhi,    g_vhi);
    cudaGetSymbolAddress((void**)&vlo,    g_vlo);
    cudaGetSymbolAddress((void**)&logits, g_logits);
    cudaGetSymbolAddress((void**)&lse,    g_lse);
    cudaGetSymbolAddress((void**)&tval,   g_tval);

    // ---- kernel instantiations + opt-in dynamic smem ----
    // big plain (128x128)
    auto kWq  = tgemm_k<128,128,64,32,true ,false,false,1,0,false,false>;
    auto kQK  = tgemm_k<128,128,64,32,true ,false,false,0,0,false,false>;
    auto kPV  = tgemm_k<128,128,64,32,false,false,false,2,0,false,false>;
    auto kWd  = tgemm_k<128,128,64,32,true ,true ,false,0,0,false,false>;
    // small plain (64x64)
    auto kS1  = tgemm_k<64,64,32,16,false,true ,false,4,2,false,false>;
    auto kS2  = tgemm_k<64,64,32,16,false,false,true ,0,0,false,false>;
    auto kWo  = tgemm_k<64,64,32,16,false,false,false,0,0,false,false>;
    // COMP head (64x64)
    auto kG1  = tgemm_k<64,64,32,16,true ,false,true ,3,0,true ,true >;
    auto kG2  = tgemm_k<64,64,32,16,true ,false,false,0,0,true ,true >;
    auto kG3  = tgemm_k<64,64,32,16,false,false,false,0,0,true ,true >;
    auto kG4  = tgemm_k<64,64,32,16,false,false,false,0,0,true ,true >;
    auto kG5  = tgemm_k<64,64,32,16,true ,false,false,0,0,true ,false>;

    constexpr int SM_BT = smem_bytes<128,128,true ,false>();  // 73728
    constexpr int SM_BN = smem_bytes<128,128,false,false>();  // 71680
    constexpr int SM_ST = smem_bytes<64,64,true ,false>();    // 36864
    constexpr int SM_SN = smem_bytes<64,64,false,false>();    // 36864
    constexpr int SM_CT = smem_bytes<64,64,true ,true >();    // 73728
    constexpr int SM_CN = smem_bytes<64,64,false,true >();    // 73728

    cudaFuncSetAttribute(kWq, cudaFuncAttributeMaxDynamicSharedMemorySize, SM_BT);
    cudaFuncSetAttribute(kQK, cudaFuncAttributeMaxDynamicSharedMemorySize, SM_BT);
    cudaFuncSetAttribute(kPV, cudaFuncAttributeMaxDynamicSharedMemorySize, SM_BN);
    cudaFuncSetAttribute(kWd, cudaFuncAttributeMaxDynamicSharedMemorySize, SM_BT);
    cudaFuncSetAttribute(kG1, cudaFuncAttributeMaxDynamicSharedMemorySize, SM_CT);
    cudaFuncSetAttribute(kG2, cudaFuncAttributeMaxDynamicSharedMemorySize, SM_CT);
    cudaFuncSetAttribute(kG3, cudaFuncAttributeMaxDynamicSharedMemorySize, SM_CN);
    cudaFuncSetAttribute(kG5, cudaFuncAttributeMaxDynamicSharedMemorySize, SM_CT);

    // ---- one-time preprocessing (per launch) ----
    prep_w_k<<<(Dd*5*65536+1023)/1024,1024>>>(Wt, Wtc, Wu, wcat1, wcat2);
    split_k<<<((long)Gg*Ee+255)/256,256>>>(embed, ehi, elo, (long)Gg*Ee);
    split_k<<<(KN*Ee*Ee+255)/256,256>>>(Wkc, wkchi, wkclo, KN*Ee*Ee);
    split_k<<<(Ee*Ee+255)/256,256>>>(Wem, wemhi, wemlo, Ee*Ee);
    embed_norm_k<<<TOK,256>>>(masked, embed, xsa, acat);

    for (int d=0; d<Dd; d++){
        const float* wq  = Wq  + (long)d*KE*Ee;
        const float* wd  = Wd  + (long)d*KE*KE;
        const float* wo  = Wo  + (long)d*KE*Ee;
        const float* btd = bt  + (long)d*Ee;

        // transitions: 2 fused GEMMs
        kS1<<<dim3(4,32,2),256,SM_SN>>>(xsa,0, wcat1+(long)d*131072,0, 0, acat,0,
                                        TOK,Ee,Ee,Ee, 0, 65536, 0, 1);
        kS2<<<dim3(4,32,1),256,SM_SN>>>(acat,0, wcat2+(long)d*196608,0, btd, xsad,0,
                                        TOK,Ee,768,768, 0,0,0, 0);

        // attention
        kWq<<<dim3(16,16,1),256,SM_BT>>>(xsa,0, wq,0, 0, q2,0,
                                         TOK,KE,Ee,Ee, 0,0,0, 0);
        kQK<<<dim3(4,32,Bb),256,SM_BT>>>(q2,0, xsa,0, 0, h,0,
                                         Ll*Kk,Ll,Ee,Ee, (long)Ll*Kk*Ee, (long)Ll*Ee, (long)Ll*Kk*Ll, 0);
        softmax_k<<<Bb*Ll*Kk,256>>>(h);
        kPV<<<dim3(2,32,Bb),256,SM_BN>>>(h,0, xsa,0, 0, q,0,
                                         Ll*Kk,Ee,Ll,Ll, (long)Ll*Kk*Ll, (long)Ll*Ee, 0, 0);

        // dense -> relu -> dense
        kWd<<<dim3(16,16,1),256,SM_BT>>>(q,0, wd,0, 0, q2,0,
                                         TOK,KE,KE,KE, 0,0,0, 0);
        kWo<<<dim3(4,32,1),256,SM_SN>>>(q2,0, wo,0, 0, t1,0,
                                        TOK,Ee,KE,KE, 0,0,0, 0);

        update_norm_k<<<TOK,256>>>(xsad, t1, xsa);
    }

    // ---- head (compensated 3xTF32 with pre-split operands) ----
    split_k<<<(TOK*Ee+255)/256,256>>>(xsa, xsahi, xsalo, TOK*Ee);
    gather_split_k<<<Bb*LM,256>>>(maskp, xsa, lpthi, lptlo);

    kG1<<<dim3(16,4,1),256,SM_CT>>>(lpthi,lptlo, wkchi,wkclo, bkc, xx1hi,xx1lo,
                                    Bb*LM, KN*Ee, Ee, Ee, 0,0,0, 0);
    kG2<<<dim3(8,4,Bb),256,SM_CT>>>(xx1hi,xx1lo, xsahi,xsalo, 0, shi,slo,
                                    LM*KN, Ll, Ee, Ee, (long)LM*KN*Ee, (long)Ll*Ee, (long)LM*KN*Ll, 0);
    kG3<<<dim3(4,4,Bb),256,SM_CN>>>(shi,slo, xsahi,xsalo, 0, xxhi,xxlo,
                                    LM*KN, Ee, Ll, Ll, (long)LM*KN*Ll, (long)Ll*Ee, (long)LM*KN*Ee, 0);
    kG4<<<dim3(4,16,1),256,SM_CN>>>(xxhi,xxlo, wemhi,wemlo, 0, vhi,vlo,
                                    Bb*LM*KN, Ee, Ee, Ee, 0,0,0, 0);
    kG5<<<dim3(500,16,1),256,SM_CT>>>(vhi,vlo, ehi,elo, 0, logits,0,
                                      Bb*LM*KN, Gg, Ee, Ee, 0,0,0, 0);

    lse_k<<<Bb*LM*KN,256>>>(logits, unmasked, maskp, lse, tval);
    final_k<<<Bb,64>>>(tval, lse, out);
}